// round 3
// baseline (speedup 1.0000x reference)
#include <cuda_runtime.h>
#include <cuda_bf16.h>
#include <cstddef>

// Output row: [obj(1) | cls(80) | reg(64) | box(4)] = 149 cols, rows = B*8400
#define OUT_COLS    149
#define M_TOTAL_OUT 8400
#define K_TOTAL     256
#define THREADS     256
#define M_TILE      128
#define N_TILE      80
#define K_TILE      16

// IS_CLS = true : N=80 cls outputs from cls_feat, write cols [1,81)
// IS_CLS = false: o=0 obj, o in [1,65) reg (cols 81..144);
//                 epilogue does DFL softmax-expectation + anchor box decode (cols 145..148)
template <bool IS_CLS>
__global__ __launch_bounds__(THREADS)
void pred_kernel(const float* __restrict__ feat,     // [B, 256, M] for this level
                 const float* __restrict__ w_a,      // cls_w [80,256]  or obj_w [1,256]
                 const float* __restrict__ w_b,      // nullptr         or reg_w [64,256]
                 const float* __restrict__ bias_a,   // cls_b [80]      or obj_b [1]
                 const float* __restrict__ bias_b,   // nullptr         or reg_b [64]
                 float* __restrict__ out,
                 int M, int Wdim, int out_m_off, float stride_f)
{
    const int b      = blockIdx.y;
    const int m_base = blockIdx.x * M_TILE;
    const float* A   = feat + (size_t)b * K_TOTAL * M;

    __shared__ float As[K_TILE][M_TILE];      // [k][m]   8 KB
    __shared__ float Ws[N_TILE][K_TILE];      // [o][k]   5 KB
    __shared__ float biasS[N_TILE];

    const int tid = threadIdx.x;

    if (tid < N_TILE) {
        float bv = 0.0f;
        if (IS_CLS) {
            bv = bias_a[tid];
        } else {
            if (tid == 0)       bv = bias_a[0];
            else if (tid < 65)  bv = bias_b[tid - 1];
        }
        biasS[tid] = bv;
    }

    // compute-thread mapping: 16 x 16; each thread: 8 consecutive m, 5 strided o
    const int tx = tid & 15;   // m group
    const int ty = tid >> 4;   // o base (0..15)
    const int mm = tx * 8;

    // A loader mapping (2 float4 per thread): 16 k-rows x 32 float4/row
    const int lk0 = tid >> 5;                 // 0..7
    const int lm0 = (tid & 31) * 4;
    const int lk1 = (tid + THREADS) >> 5;     // 8..15
    const int lm1 = lm0;

    // W loader mapping (5 scalars per thread): idx = tid + t*256, k fast
    float acc[8][5];
#pragma unroll
    for (int i = 0; i < 8; i++)
#pragma unroll
        for (int j = 0; j < 5; j++) acc[i][j] = 0.0f;

    float4 a_pf[2];
    float  w_pf[5];

    // ---- prefetch helpers (inlined manually via lambda) ----
    auto load_tiles = [&](int k0) {
        // A tile
#pragma unroll
        for (int t = 0; t < 2; t++) {
            const int lk = t ? lk1 : lk0;
            const int lm = t ? lm1 : lm0;
            const float* src = A + (size_t)(k0 + lk) * M + m_base + lm;
            float4 v;
            if (m_base + lm + 3 < M) {
                v = *reinterpret_cast<const float4*>(src);
            } else {
                v.x = (m_base + lm + 0 < M) ? src[0] : 0.0f;
                v.y = (m_base + lm + 1 < M) ? src[1] : 0.0f;
                v.z = (m_base + lm + 2 < M) ? src[2] : 0.0f;
                v.w = (m_base + lm + 3 < M) ? src[3] : 0.0f;
            }
            a_pf[t] = v;
        }
        // W tile: 1280 elems, 5 per thread
#pragma unroll
        for (int t = 0; t < 5; t++) {
            const int idx = tid + t * THREADS;
            const int k = idx & (K_TILE - 1);
            const int o = idx >> 4;
            float wv = 0.0f;
            if (IS_CLS) {
                wv = w_a[(size_t)o * K_TOTAL + k0 + k];
            } else {
                if (o == 0)      wv = w_a[k0 + k];
                else if (o < 65) wv = w_b[(size_t)(o - 1) * K_TOTAL + k0 + k];
            }
            w_pf[t] = wv;
        }
    };

    auto store_tiles = [&]() {
        *reinterpret_cast<float4*>(&As[lk0][lm0]) = a_pf[0];
        *reinterpret_cast<float4*>(&As[lk1][lm1]) = a_pf[1];
#pragma unroll
        for (int t = 0; t < 5; t++) {
            const int idx = tid + t * THREADS;
            Ws[idx >> 4][idx & (K_TILE - 1)] = w_pf[t];
        }
    };

    load_tiles(0);

    for (int k0 = 0; k0 < K_TOTAL; k0 += K_TILE) {
        store_tiles();
        __syncthreads();

        // issue next tile's global loads before the FMA body (latency overlap)
        if (k0 + K_TILE < K_TOTAL) load_tiles(k0 + K_TILE);

#pragma unroll
        for (int k = 0; k < K_TILE; k++) {
            const float4 a0 = *reinterpret_cast<const float4*>(&As[k][mm]);
            const float4 a1 = *reinterpret_cast<const float4*>(&As[k][mm + 4]);
            float wv[5];
#pragma unroll
            for (int j = 0; j < 5; j++) wv[j] = Ws[ty + 16 * j][k];
#pragma unroll
            for (int j = 0; j < 5; j++) {
                acc[0][j] = fmaf(a0.x, wv[j], acc[0][j]);
                acc[1][j] = fmaf(a0.y, wv[j], acc[1][j]);
                acc[2][j] = fmaf(a0.z, wv[j], acc[2][j]);
                acc[3][j] = fmaf(a0.w, wv[j], acc[3][j]);
                acc[4][j] = fmaf(a1.x, wv[j], acc[4][j]);
                acc[5][j] = fmaf(a1.y, wv[j], acc[5][j]);
                acc[6][j] = fmaf(a1.z, wv[j], acc[6][j]);
                acc[7][j] = fmaf(a1.w, wv[j], acc[7][j]);
            }
        }
        __syncthreads();
    }

    // ------------------------- epilogue -------------------------
    if constexpr (IS_CLS) {
#pragma unroll
        for (int i = 0; i < 8; i++) {
            const int m = m_base + mm + i;
            if (m < M) {
                const size_t row = ((size_t)b * M_TOTAL_OUT + out_m_off + m) * OUT_COLS;
#pragma unroll
                for (int j = 0; j < 5; j++) {
                    const int o = ty + 16 * j;
                    out[row + 1 + o] = acc[i][j] + biasS[o];
                }
            }
        }
    } else {
        __shared__ float regS[M_TILE][65];   // [m][reg bin], padded to 65 banks
#pragma unroll
        for (int i = 0; i < 8; i++) {
            const int m = m_base + mm + i;
            const bool valid = (m < M);
            const size_t row = valid ? ((size_t)b * M_TOTAL_OUT + out_m_off + m) * OUT_COLS : 0;
#pragma unroll
            for (int j = 0; j < 5; j++) {
                const int o = ty + 16 * j;
                const float v = acc[i][j] + biasS[o];
                if (o == 0) {
                    if (valid) out[row + 0] = v;                  // obj
                } else if (o < 65) {
                    if (valid) out[row + 81 + (o - 1)] = v;       // raw reg
                    regS[mm + i][o - 1] = v;
                }
            }
        }
        __syncthreads();

        // DFL + box decode: 256 threads = 128 m x 2 side-pairs (each does 2 sides)
        const int me = tid >> 1;
        const int m  = m_base + me;
        if (m < M) {
            const int   x  = m % Wdim;
            const int   y  = m / Wdim;
            const float ax = ((float)x + 0.5f) * stride_f;
            const float ay = ((float)y + 0.5f) * stride_f;
            const size_t row = ((size_t)b * M_TOTAL_OUT + out_m_off + m) * OUT_COLS;
#pragma unroll
            for (int s = 0; s < 2; s++) {
                const int side = (tid & 1) * 2 + s;   // 0..3
                float vals[16];
                float vmax = -1e30f;
#pragma unroll
                for (int r = 0; r < 16; r++) {
                    vals[r] = regS[me][side * 16 + r];
                    vmax = fmaxf(vmax, vals[r]);
                }
                float sum = 0.0f, dot = 0.0f;
#pragma unroll
                for (int r = 0; r < 16; r++) {
                    const float e = __expf(vals[r] - vmax);
                    sum += e;
                    dot = fmaf(e, (16.0f / 15.0f) * (float)r, dot);  // proj = linspace(0,16,16)
                }
                const float d = dot / sum;
                float coord;
                if      (side == 0) coord = ax - d * stride_f;  // x1
                else if (side == 1) coord = ay - d * stride_f;  // y1
                else if (side == 2) coord = ax + d * stride_f;  // x2
                else                coord = ay + d * stride_f;  // y2
                out[row + 145 + side] = coord;
            }
        }
    }
}

extern "C" void kernel_launch(void* const* d_in, const int* in_sizes, int n_in,
                              void* d_out, int out_size)
{
    // Feature ordering may be dict order (cls0,reg0,cls1,reg1,cls2,reg2) or
    // signature order (cls0,cls1,cls2,reg0,reg1,reg2). Disambiguate by size:
    // interleaved <=> sizes[0]==sizes[1] (cls/reg same shape per level).
    const bool interleaved = (in_sizes[1] == in_sizes[0]);
    const float* cls_feat[3];
    const float* reg_feat[3];
    for (int l = 0; l < 3; l++) {
        if (interleaved) {
            cls_feat[l] = (const float*)d_in[2 * l + 0];
            reg_feat[l] = (const float*)d_in[2 * l + 1];
        } else {
            cls_feat[l] = (const float*)d_in[l];
            reg_feat[l] = (const float*)d_in[3 + l];
        }
    }

    const int   Hs[3]      = {80, 40, 20};
    const int   Wd[3]      = {80, 40, 20};
    const float strides[3] = {8.0f, 16.0f, 32.0f};
    const int   B          = 16;

    int m_off = 0;
    for (int l = 0; l < 3; l++) {
        // weight group order per level: obj_w, obj_b, cls_w, cls_b, reg_w, reg_b
        const float* obj_w = (const float*)d_in[6 + 6 * l + 0];
        const float* obj_b = (const float*)d_in[6 + 6 * l + 1];
        const float* cls_w = (const float*)d_in[6 + 6 * l + 2];
        const float* cls_b = (const float*)d_in[6 + 6 * l + 3];
        const float* reg_w = (const float*)d_in[6 + 6 * l + 4];
        const float* reg_b = (const float*)d_in[6 + 6 * l + 5];

        const int M = Hs[l] * Wd[l];
        dim3 grid((M + M_TILE - 1) / M_TILE, B);

        pred_kernel<true ><<<grid, THREADS>>>(cls_feat[l], cls_w, nullptr, cls_b, nullptr,
                                              (float*)d_out, M, Wd[l], m_off, strides[l]);
        pred_kernel<false><<<grid, THREADS>>>(reg_feat[l], obj_w, reg_w, obj_b, reg_b,
                                              (float*)d_out, M, Wd[l], m_off, strides[l]);
        m_off += M;
    }
}

// round 7
// speedup vs baseline: 1.7902x; 1.7902x over previous
#include <cuda_runtime.h>
#include <cstddef>
#include <cstdint>

// Output row: [obj(1) | cls(80) | reg(64) | box(4)] = 149 cols, rows = B*8400
#define OUT_COLS   149
#define ROWS_PER_B 8400
#define K_TOTAL    256
#define THREADS    256
#define K_TILE     16
#define N_TILE     80
#define NSTAGE     (K_TOTAL / K_TILE)   // 16

__device__ __forceinline__ unsigned su32(const void* p) {
    return (unsigned)__cvta_generic_to_shared(p);
}

// MPT = m-values per thread (12 -> M_TILE=192, 8 -> M_TILE=128)
// IS_CLS = true : 80 cls outputs from cls_feat -> cols [1,81)
// IS_CLS = false: o=0 obj (col 0), o in [1,65) reg (cols 81..144); o>=65 padding
template<int MPT, bool IS_CLS>
__global__ __launch_bounds__(THREADS, 2)
void gemm_kernel(const float* __restrict__ feat,     // [B, 256, M] for this level
                 const float* __restrict__ w_a,      // cls_w [80,256] or obj_w [1,256]
                 const float* __restrict__ w_b,      // nullptr        or reg_w [64,256]
                 const float* __restrict__ bias_a,
                 const float* __restrict__ bias_b,
                 float* __restrict__ out,
                 int M, int out_m_off)
{
    constexpr int M_TILE = MPT * 16;
    constexpr int NCH    = MPT / 4;                       // LDS.128 chunks per thread per k
    constexpr int NF4    = K_TILE * M_TILE / 4 / THREADS; // cp.async float4 per thread per stage

    __shared__ float  As[2][K_TILE][M_TILE];              // double-buffered A tile
    __shared__ float2 Ws2[N_TILE][K_TILE + 1];            // (w,w) pairs, padded row
    __shared__ float  biasS[N_TILE];

    const int tid    = threadIdx.x;
    const int b      = blockIdx.y;
    const int m_base = blockIdx.x * M_TILE;
    const float* A   = feat + (size_t)b * K_TOTAL * M;

    if (tid < N_TILE) {
        float bv;
        if (IS_CLS) bv = bias_a[tid];
        else        bv = (tid == 0) ? bias_a[0] : (tid < 65 ? bias_b[tid - 1] : 0.0f);
        biasS[tid] = bv;
    }

    const int tx = tid & 15;        // m group
    const int ty = tid >> 4;        // o group (0..15)
    const int o0 = ty * 5;          // 5 consecutive outputs per thread

    // ---- A tile loader: cp.async 16B with zfill tail handling ----
    auto issue_A = [&](int stage, int buf) {
#pragma unroll
        for (int t = 0; t < NF4; t++) {
            const int idx = tid + t * THREADS;
            const int lk  = idx / (M_TILE / 4);
            const int lf  = idx % (M_TILE / 4);
            const float* src = A + (size_t)(stage * K_TILE + lk) * M + m_base + lf * 4;
            const int rem   = M - (m_base + lf * 4);
            const int bytes = rem >= 4 ? 16 : (rem > 0 ? rem * 4 : 0);
            const unsigned dst = su32(&As[buf][lk][lf * 4]);
            asm volatile("cp.async.cg.shared.global [%0], [%1], 16, %2;\n"
                         :: "r"(dst), "l"(src), "r"(bytes));
        }
        asm volatile("cp.async.commit_group;\n");
    };

    // ---- W register prefetch (5 scalars/thread), stored duplicated to smem ----
    float w_pf[5];
    auto load_W = [&](int stage) {
#pragma unroll
        for (int t = 0; t < 5; t++) {
            const int idx = tid + t * THREADS;   // 0..1279
            const int o   = idx >> 4;
            const int k   = idx & 15;
            float wv = 0.0f;
            if (IS_CLS) {
                wv = w_a[(size_t)o * K_TOTAL + stage * K_TILE + k];
            } else {
                if (o == 0)      wv = w_a[stage * K_TILE + k];
                else if (o < 65) wv = w_b[(size_t)(o - 1) * K_TOTAL + stage * K_TILE + k];
            }
            w_pf[t] = wv;
        }
    };
    auto store_W = [&]() {
#pragma unroll
        for (int t = 0; t < 5; t++) {
            const int idx = tid + t * THREADS;
            Ws2[idx >> 4][idx & 15] = make_float2(w_pf[t], w_pf[t]);
        }
    };

    unsigned long long acc[NCH][2][5];
#pragma unroll
    for (int c = 0; c < NCH; c++)
#pragma unroll
        for (int p = 0; p < 2; p++)
#pragma unroll
            for (int j = 0; j < 5; j++) acc[c][p][j] = 0ull;

    // ---- prologue ----
    load_W(0);
    issue_A(0, 0);
    issue_A(1, 1);
    store_W();          // Ws2 for stage 0 (visible after first in-loop barrier)
    load_W(1);

    // ---- main loop over K stages ----
    for (int t = 0; t < NSTAGE; t++) {
        if (t < NSTAGE - 1) asm volatile("cp.async.wait_group 1;\n" ::: "memory");
        else                asm volatile("cp.async.wait_group 0;\n" ::: "memory");
        __syncthreads();
        const int buf = t & 1;

#pragma unroll
        for (int k = 0; k < K_TILE; k++) {
            unsigned long long w2[5];
#pragma unroll
            for (int j = 0; j < 5; j++)
                w2[j] = *reinterpret_cast<const unsigned long long*>(&Ws2[o0 + j][k]);
#pragma unroll
            for (int c = 0; c < NCH; c++) {
                union { float4 f; unsigned long long u[2]; } a;
                // lanes contiguous at 16B stride -> conflict-free LDS.128
                a.f = *reinterpret_cast<const float4*>(&As[buf][k][tx * 4 + c * 64]);
#pragma unroll
                for (int j = 0; j < 5; j++) {
                    asm("fma.rn.f32x2 %0, %1, %2, %0;" : "+l"(acc[c][0][j]) : "l"(a.u[0]), "l"(w2[j]));
                    asm("fma.rn.f32x2 %0, %1, %2, %0;" : "+l"(acc[c][1][j]) : "l"(a.u[1]), "l"(w2[j]));
                }
            }
        }
        __syncthreads();

        if (t + 2 < NSTAGE) issue_A(t + 2, buf);   // refill buffer just consumed
        if (t + 1 < NSTAGE) store_W();             // W for stage t+1
        if (t + 2 < NSTAGE) load_W(t + 2);
    }

    // ---- epilogue: bias + scattered stores (L2 merges sectors) ----
    const size_t row_base = (size_t)b * ROWS_PER_B + out_m_off;
#pragma unroll
    for (int c = 0; c < NCH; c++) {
#pragma unroll
        for (int j = 0; j < 5; j++) {
            const int o = o0 + j;
            union { unsigned long long u; float2 f; } lo, hi;
            lo.u = acc[c][0][j];
            hi.u = acc[c][1][j];
            const float vals[4] = {lo.f.x, lo.f.y, hi.f.x, hi.f.y};
            const float bv = biasS[o];
#pragma unroll
            for (int i = 0; i < 4; i++) {
                const int m = m_base + tx * 4 + c * 64 + i;
                if (m < M) {
                    const size_t row = (row_base + m) * OUT_COLS;
                    if (IS_CLS) {
                        out[row + 1 + o] = vals[i] + bv;
                    } else {
                        if (o == 0)      out[row + 0]            = vals[i] + bv;
                        else if (o < 65) out[row + 81 + (o - 1)] = vals[i] + bv;
                    }
                }
            }
        }
    }
}

// DFL softmax-expectation + anchor box decode, reading reg cols back via L2.
__global__ void dfl_kernel(float* __restrict__ out, int total_rows)
{
    const int gid = blockIdx.x * blockDim.x + threadIdx.x;
    if (gid >= total_rows * 4) return;
    const int side = gid & 3;
    const int row  = gid >> 2;
    const int mg   = row % ROWS_PER_B;

    int Wd, mloc; float stride_f;
    if (mg < 6400)      { Wd = 80; stride_f = 8.0f;  mloc = mg; }
    else if (mg < 8000) { Wd = 40; stride_f = 16.0f; mloc = mg - 6400; }
    else                { Wd = 20; stride_f = 32.0f; mloc = mg - 8000; }

    const float* p = out + (size_t)row * OUT_COLS + 81 + side * 16;
    float v[16], vmax = -1e30f;
#pragma unroll
    for (int r = 0; r < 16; r++) { v[r] = p[r]; vmax = fmaxf(vmax, v[r]); }
    float sum = 0.0f, dot = 0.0f;
#pragma unroll
    for (int r = 0; r < 16; r++) {
        const float e = __expf(v[r] - vmax);
        sum += e;
        dot = fmaf(e, (16.0f / 15.0f) * (float)r, dot);   // proj = linspace(0,16,16)
    }
    const float d  = dot / sum;
    const int   x  = mloc % Wd;
    const int   y  = mloc / Wd;
    const float ax = ((float)x + 0.5f) * stride_f;
    const float ay = ((float)y + 0.5f) * stride_f;
    float coord;
    if      (side == 0) coord = ax - d * stride_f;
    else if (side == 1) coord = ay - d * stride_f;
    else if (side == 2) coord = ax + d * stride_f;
    else                coord = ay + d * stride_f;
    out[(size_t)row * OUT_COLS + 145 + side] = coord;
}

extern "C" void kernel_launch(void* const* d_in, const int* in_sizes, int n_in,
                              void* d_out, int out_size)
{
    // Feature ordering: dict-interleaved (cls0,reg0,...) vs signature (cls0..2,reg0..2),
    // disambiguated by size (interleaved <=> sizes[0]==sizes[1]).
    const bool interleaved = (in_sizes[1] == in_sizes[0]);
    const float* cls_feat[3];
    const float* reg_feat[3];
    for (int l = 0; l < 3; l++) {
        if (interleaved) {
            cls_feat[l] = (const float*)d_in[2 * l + 0];
            reg_feat[l] = (const float*)d_in[2 * l + 1];
        } else {
            cls_feat[l] = (const float*)d_in[l];
            reg_feat[l] = (const float*)d_in[3 + l];
        }
    }

    const int Ms[3]    = {6400, 1600, 400};
    const int moffs[3] = {0, 6400, 8000};
    const int B        = 16;
    float* out = (float*)d_out;

    for (int l = 0; l < 3; l++) {
        const float* obj_w = (const float*)d_in[6 + 6 * l + 0];
        const float* obj_b = (const float*)d_in[6 + 6 * l + 1];
        const float* cls_w = (const float*)d_in[6 + 6 * l + 2];
        const float* cls_b = (const float*)d_in[6 + 6 * l + 3];
        const float* reg_w = (const float*)d_in[6 + 6 * l + 4];
        const float* reg_b = (const float*)d_in[6 + 6 * l + 5];
        const int M = Ms[l];

        if (l == 0) {
            dim3 grid((M + 191) / 192, B);
            gemm_kernel<12, true ><<<grid, THREADS>>>(cls_feat[l], cls_w, nullptr, cls_b, nullptr,
                                                      out, M, moffs[l]);
            gemm_kernel<12, false><<<grid, THREADS>>>(reg_feat[l], obj_w, reg_w, obj_b, reg_b,
                                                      out, M, moffs[l]);
        } else {
            dim3 grid((M + 127) / 128, B);
            gemm_kernel<8, true ><<<grid, THREADS>>>(cls_feat[l], cls_w, nullptr, cls_b, nullptr,
                                                     out, M, moffs[l]);
            gemm_kernel<8, false><<<grid, THREADS>>>(reg_feat[l], obj_w, reg_w, obj_b, reg_b,
                                                     out, M, moffs[l]);
        }
    }

    const int total_rows = B * ROWS_PER_B;          // 134400
    const int nthr = total_rows * 4;                // one thread per (row, side)
    dfl_kernel<<<(nthr + 255) / 256, 256>>>(out, total_rows);
}

// round 11
// speedup vs baseline: 2.7494x; 1.5358x over previous
#include <cuda_runtime.h>
#include <cuda_bf16.h>
#include <cstdint>
#include <cstddef>

// Output row: [obj(1) | cls(80) | reg(64) | box(4)] = 149 cols, rows = B*8400
#define OUT_COLS   149
#define ROWS_PER_B 8400
#define NT         256

#define TILE_M 128
#define TILE_K 64              // fp32 k per stage
#define NSTG   4               // 256 / 64

// smem layout (bytes). A tile: [64 k][256B = 128 m bf16]; W tile: [80 n][128B = 64 k bf16]
#define SM_BIAS   0            // 80 floats
#define BUF_BASE  1024
#define OFF_AH    0
#define OFF_AL    16384
#define OFF_WH    32768
#define OFF_WL    43008
#define BUF_SZ    53248
#define SMEM_TOTAL (BUF_BASE + 2 * BUF_SZ)   // 107520

// SW128 swizzle for 128B rows (W tile)
#define SWZ(off) ((off) ^ (((off) >> 3) & 0x70))
// A tile swizzle: 256B rows, 16B chunk index XOR'd with (k & 7)
__device__ __forceinline__ uint32_t aswz(int krow, int mbyte) {
    return (uint32_t)krow * 256 + ((((mbyte >> 4) ^ (krow & 7)) & 15) << 4) + (mbyte & 15);
}

__device__ __forceinline__ uint32_t smem_u32(const void* p) {
    return (uint32_t)__cvta_generic_to_shared(p);
}

#define LDSM4T(r, a)                                                            \
    asm volatile("ldmatrix.sync.aligned.m8n8.x4.trans.shared.b16 "              \
                 "{%0,%1,%2,%3}, [%4];"                                         \
                 : "=r"((r)[0]), "=r"((r)[1]), "=r"((r)[2]), "=r"((r)[3])       \
                 : "r"(a))

#define LDSM2(r, a)                                                             \
    asm volatile("ldmatrix.sync.aligned.m8n8.x2.shared.b16 {%0,%1}, [%2];"      \
                 : "=r"((r)[0]), "=r"((r)[1]) : "r"(a))

#define MMA16816(c, A_, B_)                                                     \
    asm volatile("mma.sync.aligned.m16n8k16.row.col.f32.bf16.bf16.f32 "         \
                 "{%0,%1,%2,%3}, {%4,%5,%6,%7}, {%8,%9}, {%0,%1,%2,%3};"        \
                 : "+f"((c)[0]), "+f"((c)[1]), "+f"((c)[2]), "+f"((c)[3])       \
                 : "r"((A_)[0]), "r"((A_)[1]), "r"((A_)[2]), "r"((A_)[3]),      \
                   "r"((B_)[0]), "r"((B_)[1]))

// bf16 two-term split, packing (x, y) as bf16x2
__device__ __forceinline__ uint32_t split_pack(float a, float b, uint32_t& lo_out) {
    __nv_bfloat16 ha = __float2bfloat16(a);
    __nv_bfloat16 hb = __float2bfloat16(b);
    __nv_bfloat16 la = __float2bfloat16(a - __bfloat162float(ha));
    __nv_bfloat16 lb = __float2bfloat16(b - __bfloat162float(hb));
    lo_out = (uint32_t)__bfloat16_as_ushort(la) | ((uint32_t)__bfloat16_as_ushort(lb) << 16);
    return (uint32_t)__bfloat16_as_ushort(ha) | ((uint32_t)__bfloat16_as_ushort(hb) << 16);
}

struct LvlP { const float* feat; const float* w_a; const float* w_b;
              const float* ba;   const float* bb; };
struct AllP { LvlP p[2][3]; };   // [type][level]: type 0=cls, 1=obj+reg

__global__ __launch_bounds__(NT, 2)
void hmma_kernel(AllP ap, float* __restrict__ out)
{
    extern __shared__ char smem[];
    const uint32_t sbase = smem_u32(smem);
    const int tid  = threadIdx.x;
    const int wid  = tid >> 5;
    const int lane = tid & 31;
    const int warp_m = wid >> 1;      // 0..3 -> m rows warp_m*32
    const int warp_n = wid & 1;       // 0..1 -> n cols warp_n*40

    // decode (level, tile) from blockIdx.x: tiles {50, 13, 4}
    const int bx = blockIdx.x, b = blockIdx.y, type = blockIdx.z;
    int level, tile;
    if (bx < 50)      { level = 0; tile = bx; }
    else if (bx < 63) { level = 1; tile = bx - 50; }
    else              { level = 2; tile = bx - 63; }
    const int M    = (level == 0) ? 6400 : (level == 1 ? 1600 : 400);
    const int moff = (level == 0) ? 0    : (level == 1 ? 6400 : 8000);
    const int m_base = tile * TILE_M;

    const LvlP pr = ap.p[type][level];
    const float* A = pr.feat + (size_t)b * 256 * M;

    float* biasS = (float*)(smem + SM_BIAS);
    if (tid < 80) {
        float bv;
        if (type == 0) bv = pr.ba[tid];
        else bv = (tid == 0) ? pr.ba[0] : (tid < 65 ? pr.bb[tid - 1] : 0.0f);
        biasS[tid] = bv;
    }

    // ---- stage fill: fp32 -> bf16 hi/lo into swizzled smem ----
    // A: [k][m] 256B rows: LDG.128 coalesced on m, STS conflict-free (k fixed per warp)
    auto fill = [&](int s, int buf) {
        const int k0 = s * TILE_K;
        char* bb_ = smem + BUF_BASE + buf * BUF_SZ;
#pragma unroll
        for (int i = 0; i < 8; i++) {
            const int task = tid + i * NT;       // 0..2047
            const int krow = task >> 5;          // 0..63
            const int m0   = (task & 31) * 4;    // 0..124
            const float* src = A + (size_t)(k0 + krow) * M + m_base + m0;
            float4 v;
            if (m_base + m0 + 3 < M) {
                v = *reinterpret_cast<const float4*>(src);
            } else {
                v.x = (m_base + m0 + 0 < M) ? src[0] : 0.0f;
                v.y = (m_base + m0 + 1 < M) ? src[1] : 0.0f;
                v.z = (m_base + m0 + 2 < M) ? src[2] : 0.0f;
                v.w = (m_base + m0 + 3 < M) ? src[3] : 0.0f;
            }
            uint32_t lo0, hi0 = split_pack(v.x, v.y, lo0);
            uint32_t lo1, hi1 = split_pack(v.z, v.w, lo1);
            const uint32_t off = aswz(krow, m0 * 2);   // +4 stays in same 16B chunk
            *reinterpret_cast<uint32_t*>(bb_ + OFF_AH + off)     = hi0;
            *reinterpret_cast<uint32_t*>(bb_ + OFF_AH + off + 4) = hi1;
            *reinterpret_cast<uint32_t*>(bb_ + OFF_AL + off)     = lo0;
            *reinterpret_cast<uint32_t*>(bb_ + OFF_AL + off + 4) = lo1;
        }
        // W: [n][k] 128B rows, SW128: 80 o x 16 float4 = 1280 tasks, 5/thread
#pragma unroll
        for (int i = 0; i < 5; i++) {
            const int task = tid + i * NT;
            const int o = task >> 4;
            const int k = (task & 15) * 4;
            float w4[4] = {0, 0, 0, 0};
            const float* src = nullptr;
            if (type == 0)            src = pr.w_a + (size_t)o * 256 + k0 + k;
            else if (o == 0)          src = pr.w_a + k0 + k;
            else if (o < 65)          src = pr.w_b + (size_t)(o - 1) * 256 + k0 + k;
            if (src) {
                float4 v = *reinterpret_cast<const float4*>(src);
                w4[0] = v.x; w4[1] = v.y; w4[2] = v.z; w4[3] = v.w;
            }
#pragma unroll
            for (int pp = 0; pp < 2; pp++) {
                uint32_t lo, hi = split_pack(w4[2 * pp], w4[2 * pp + 1], lo);
                const uint32_t off = SWZ((uint32_t)o * 128 + (uint32_t)(k + 2 * pp) * 2);
                *reinterpret_cast<uint32_t*>(bb_ + OFF_WH + off) = hi;
                *reinterpret_cast<uint32_t*>(bb_ + OFF_WL + off) = lo;
            }
        }
    };

    float acc[2][5][4];
#pragma unroll
    for (int mi = 0; mi < 2; mi++)
#pragma unroll
        for (int ni = 0; ni < 5; ni++)
#pragma unroll
            for (int r = 0; r < 4; r++) acc[mi][ni][r] = 0.0f;

    const int l7  = lane & 7;
    const int l8  = (lane >> 3) & 1;
    const int l16 = (lane >> 4) & 1;

    fill(0, 0);
    __syncthreads();

    for (int t = 0; t < NSTG; t++) {
        if (t + 1 < NSTG) fill(t + 1, (t + 1) & 1);   // other buffer; LDG latency overlaps MMAs

        const uint32_t bb_ = sbase + BUF_BASE + (t & 1) * BUF_SZ;
        const uint32_t Ah = bb_ + OFF_AH, Al = bb_ + OFF_AL;
        const uint32_t Wh = bb_ + OFF_WH, Wl = bb_ + OFF_WL;

#pragma unroll
        for (int kk = 0; kk < 4; kk++) {       // 4 x k16 per stage
            uint32_t ah[2][4], al[2][4];
#pragma unroll
            for (int mi = 0; mi < 2; mi++) {
                // trans x4: lanes 0-7: S rows k..k+7 @ m-chunk; 8-15: +16B; 16-23: rows k+8; 24-31: both
                const int krow  = kk * 16 + l7 + l16 * 8;
                const int mbyte = (warp_m * 32 + mi * 16) * 2 + l8 * 16;
                const uint32_t off = aswz(krow, mbyte);
                LDSM4T(ah[mi], Ah + off);
                LDSM4T(al[mi], Al + off);
            }
#pragma unroll
            for (int ni = 0; ni < 5; ni++) {
                // non-trans x2: lanes 0-7: W rows n..n+7 @ k-chunk; 8-15: +16B
                const int n = warp_n * 40 + ni * 8 + l7;
                const uint32_t off = SWZ((uint32_t)n * 128 + (uint32_t)kk * 32 + (uint32_t)l8 * 16);
                uint32_t bh[2], bl[2];
                LDSM2(bh, Wh + off);
                LDSM2(bl, Wl + off);
                MMA16816(acc[0][ni], ah[0], bh);
                MMA16816(acc[1][ni], ah[1], bh);
                MMA16816(acc[0][ni], ah[0], bl);
                MMA16816(acc[1][ni], ah[1], bl);
                MMA16816(acc[0][ni], al[0], bh);
                MMA16816(acc[1][ni], al[1], bh);
            }
        }
        __syncthreads();
    }

    // ---- epilogue: bias + scattered stores (L2 merges sectors) ----
    const int g  = lane >> 2;
    const int t4 = lane & 3;
    const size_t row_base = (size_t)b * ROWS_PER_B + moff;
#pragma unroll
    for (int mi = 0; mi < 2; mi++) {
#pragma unroll
        for (int rr = 0; rr < 2; rr++) {
            const int m = m_base + warp_m * 32 + mi * 16 + g + rr * 8;
            if (m < M) {
                const size_t row = (row_base + m) * OUT_COLS;
#pragma unroll
                for (int ni = 0; ni < 5; ni++) {
                    const int c0 = warp_n * 40 + ni * 8 + t4 * 2;
#pragma unroll
                    for (int e = 0; e < 2; e++) {
                        const int c = c0 + e;
                        const float v = acc[mi][ni][rr * 2 + e] + biasS[c];
                        if (type == 0) {
                            out[row + 1 + c] = v;
                        } else {
                            if (c == 0)      out[row]          = v;
                            else if (c < 65) out[row + 80 + c] = v;
                        }
                    }
                }
            }
        }
    }
}

// DFL softmax-expectation + anchor box decode, reading reg cols back via L2.
__global__ void dfl_kernel(float* __restrict__ out, int total_rows)
{
    const int gid = blockIdx.x * blockDim.x + threadIdx.x;
    if (gid >= total_rows * 4) return;
    const int side = gid & 3;
    const int row  = gid >> 2;
    const int mg   = row % ROWS_PER_B;

    int Wd, mloc; float stride_f;
    if (mg < 6400)      { Wd = 80; stride_f = 8.0f;  mloc = mg; }
    else if (mg < 8000) { Wd = 40; stride_f = 16.0f; mloc = mg - 6400; }
    else                { Wd = 20; stride_f = 32.0f; mloc = mg - 8000; }

    const float* p = out + (size_t)row * OUT_COLS + 81 + side * 16;
    float v[16], vmax = -1e30f;
#pragma unroll
    for (int r = 0; r < 16; r++) { v[r] = p[r]; vmax = fmaxf(vmax, v[r]); }
    float sum = 0.0f, dot = 0.0f;
#pragma unroll
    for (int r = 0; r < 16; r++) {
        const float e = __expf(v[r] - vmax);
        sum += e;
        dot = fmaf(e, (16.0f / 15.0f) * (float)r, dot);   // proj = linspace(0,16,16)
    }
    const float d  = dot / sum;
    const int   x  = mloc % Wd;
    const int   y  = mloc / Wd;
    const float ax = ((float)x + 0.5f) * stride_f;
    const float ay = ((float)y + 0.5f) * stride_f;
    float coord;
    if      (side == 0) coord = ax - d * stride_f;
    else if (side == 1) coord = ay - d * stride_f;
    else if (side == 2) coord = ax + d * stride_f;
    else                coord = ay + d * stride_f;
    out[(size_t)row * OUT_COLS + 145 + side] = coord;
}

extern "C" void kernel_launch(void* const* d_in, const int* in_sizes, int n_in,
                              void* d_out, int out_size)
{
    // Feature ordering: dict-interleaved (cls0,reg0,...) vs signature (cls0..2,reg0..2),
    // disambiguated by size (interleaved <=> sizes[0]==sizes[1]).
    const bool interleaved = (in_sizes[1] == in_sizes[0]);
    AllP ap;
    for (int l = 0; l < 3; l++) {
        const float* cf, *rf;
        if (interleaved) { cf = (const float*)d_in[2 * l]; rf = (const float*)d_in[2 * l + 1]; }
        else             { cf = (const float*)d_in[l];     rf = (const float*)d_in[3 + l]; }
        const float* obj_w = (const float*)d_in[6 + 6 * l + 0];
        const float* obj_b = (const float*)d_in[6 + 6 * l + 1];
        const float* cls_w = (const float*)d_in[6 + 6 * l + 2];
        const float* cls_b = (const float*)d_in[6 + 6 * l + 3];
        const float* reg_w = (const float*)d_in[6 + 6 * l + 4];
        const float* reg_b = (const float*)d_in[6 + 6 * l + 5];
        ap.p[0][l] = { cf, cls_w, nullptr, cls_b, nullptr };   // cls
        ap.p[1][l] = { rf, obj_w, reg_w,   obj_b, reg_b  };    // obj+reg
    }

    float* out = (float*)d_out;
    cudaFuncSetAttribute(hmma_kernel, cudaFuncAttributeMaxDynamicSharedMemorySize, SMEM_TOTAL);

    dim3 grid(67, 16, 2);   // 50+13+4 m-tiles, 16 batch, {cls, reg}
    hmma_kernel<<<grid, NT, SMEM_TOTAL>>>(ap, out);

    const int total_rows = 16 * ROWS_PER_B;   // 134400
    const int nthr = total_rows * 4;
    dfl_kernel<<<(nthr + 255) / 256, 256>>>(out, total_rows);
}